// round 8
// baseline (speedup 1.0000x reference)
#include <cuda_runtime.h>
#include <cuda_bf16.h>
#include <cstddef>

// x[64,512,128] @ Wx[128,1024] + b -> XP (in d_out); then
// h_t = tanh(xp_t + h_{t-1} @ Wh[1024,1024]); out[b,t,:] = h_t.
#define BB 64
#define TT 512
#define DD 128
#define HH 1024

typedef unsigned long long ull;

__device__ __forceinline__ ull pk2(float lo, float hi) {
    ull r; asm("mov.b64 %0, {%1, %2};" : "=l"(r) : "f"(lo), "f"(hi)); return r;
}
__device__ __forceinline__ float2 upk2(ull v) {
    float lo, hi; asm("mov.b64 {%0, %1}, %2;" : "=f"(lo), "=f"(hi) : "l"(v));
    return make_float2(lo, hi);
}
__device__ __forceinline__ ull ffma2(ull a, ull b, ull c) {
    ull d; asm("fma.rn.f32x2 %0, %1, %2, %3;" : "=l"(d) : "l"(a), "l"(b), "l"(c));
    return d;
}
__device__ __forceinline__ int ld_acq(const int* p) {
    int v; asm volatile("ld.acquire.gpu.global.s32 %0, [%1];" : "=r"(v) : "l"(p));
    return v;
}
__device__ __forceinline__ void red_rel_add1(int* p) {
    asm volatile("red.release.gpu.global.add.s32 [%0], 1;" :: "l"(p) : "memory");
}
// 16B L2-cached global load as packed f32x2 pair (no unpack movs)
__device__ __forceinline__ ulonglong2 ldg2(const void* p) {
    ulonglong2 v;
    asm volatile("ld.global.cg.v2.b64 {%0, %1}, [%2];"
                 : "=l"(v.x), "=l"(v.y) : "l"(p));
    return v;
}
// fast tanh: exp-based, ~1e-6 rel err; clamp avoids inf/inf.
__device__ __forceinline__ float fast_tanh(float x) {
    x = fminf(fmaxf(x, -15.f), 15.f);
    float e = __expf(x + x);
    return __fdividef(e - 1.f, e + 1.f);
}

// ---------- global scratch ----------
__device__ float g_h[2][BB][HH];         // h double buffer, row-major [b][k]
__device__ int   g_flags[4][TT][8];      // (group, step, k-chunk) warp arrivals

// =====================================================================
// Kernel 1: XP = x @ Wx + b  -> d_out   (M=32768, K=128, N=1024)
// Block (0,0) also resets the step flags.
// =====================================================================
__global__ __launch_bounds__(256) void xp_gemm(
    const float* __restrict__ x, const float* __restrict__ Wx,
    const float* __restrict__ bias, float* __restrict__ out)
{
    __shared__ float xs[64 * 68];
    __shared__ float ws[64 * 64];

    const int tid = threadIdx.x;
    if (blockIdx.x == 0 && blockIdx.y == 0) {
        int* f = &g_flags[0][0][0];
        #pragma unroll
        for (int i = tid; i < 4 * TT * 8; i += 256) f[i] = 0;
    }

    const int m0 = blockIdx.x * 64;
    const int n0 = blockIdx.y * 64;
    const int ty = tid >> 4;
    const int tx = tid & 15;

    ull acc01[4] = {0ull, 0ull, 0ull, 0ull};
    ull acc23[4] = {0ull, 0ull, 0ull, 0ull};

    for (int k0 = 0; k0 < DD; k0 += 64) {
        __syncthreads();
        #pragma unroll
        for (int i = tid; i < 1024; i += 256) {
            int r = i >> 4, q = i & 15;
            ((float4*)xs)[r * 17 + q] =
                *(const float4*)&x[(size_t)(m0 + r) * DD + k0 + 4 * q];
        }
        #pragma unroll
        for (int i = tid; i < 1024; i += 256) {
            int r = i >> 4, q = i & 15;
            ((float4*)ws)[i] =
                *(const float4*)&Wx[(size_t)(k0 + r) * HH + n0 + 4 * q];
        }
        __syncthreads();

        #pragma unroll 8
        for (int kk = 0; kk < 64; kk++) {
            ulonglong2 wv = *(const ulonglong2*)&ws[kk * 64 + 4 * tx];
            #pragma unroll
            for (int i = 0; i < 4; i++) {
                float a = xs[(4 * ty + i) * 68 + kk];
                ull aa = pk2(a, a);
                acc01[i] = ffma2(aa, wv.x, acc01[i]);
                acc23[i] = ffma2(aa, wv.y, acc23[i]);
            }
        }
    }

    float4 bv = *(const float4*)&bias[n0 + 4 * tx];
    #pragma unroll
    for (int i = 0; i < 4; i++) {
        float2 p0 = upk2(acc01[i]);
        float2 p1 = upk2(acc23[i]);
        float4 r;
        r.x = p0.x + bv.x; r.y = p0.y + bv.y;
        r.z = p1.x + bv.z; r.w = p1.y + bv.w;
        *(float4*)&out[(size_t)(m0 + 4 * ty + i) * HH + n0 + 4 * tx] = r;
    }
}

// =====================================================================
// Kernel 2: persistent recurrence with TWO independent chains per SM.
// 128 CTAs x 512 threads. CTA cid, col-slice j = cid&63 (16 cols, Wh
// slice SHARED by both halves), half 0 (warps 0-7): group cid>>6 (0/1),
// half 1 (warps 8-15): group (cid>>6)+2 (2/3). Halves never sync with
// each other -> when one half stalls on its step chain, the other
// half's warps keep the fma pipe busy.
// Per half: warp wl consumes k-chunk wl (128 k) reading h straight from
// L2 (ldg2); lane (cq=lane&7, bq=lane>>3) -> 4 batches x 2 cols,
// packed-over-k accumulators. red double-buffered by parity.
// One named barrier (id half+1, 256 thr) per step.
// Flags: chunk wl's h cols come from 8 col-slices x 8 epi-warps = 64.
// =====================================================================
#define RROW 130                 /* 8*16 + 2 pad floats per batch row */
#define RED_PAR (16 * RROW)      /* 2080 floats per parity buffer */
#define SMEM_BYTES (4096 * 16 + 2 * 2 * RED_PAR * 4)   /* 98,816 B */

__global__ __launch_bounds__(512) void rnn_persist(
    float* __restrict__ out, const float* __restrict__ Wh)
{
    extern __shared__ float4 sm4[];
    float4* wb4  = sm4;                      // [256][16] Wh K-blocked
    float*  redb = (float*)(sm4 + 4096);     // [2 halves][2 par][2080]

    const int tid  = threadIdx.x;
    const int half = tid >> 8;               // 0 or 1
    const int tid2 = tid & 255;
    const int j    = blockIdx.x & 63;        // col slice
    const int g    = (blockIdx.x >> 6) + 2 * half;
    const int B0   = 16 * g;
    const int C0   = 16 * j;
    const int jc   = j >> 3;                 // chunk this slice feeds

    // one-time: Wh slice [1024 k][16 c], K-transposed into float4 blocks.
    // col c at slot (c&1)*8+(c>>1): even cols -> slots 0-7, odd -> 8-15
    // (conflict-free LDS.128 for col pairs 2cq / 2cq+1).
    for (int idx = tid; idx < 4096; idx += 512) {
        int k4 = idx >> 4, c = idx & 15;
        const float* p = &Wh[(size_t)(4 * k4) * HH + C0 + c];
        float4 v;
        v.x = p[0]; v.y = p[HH]; v.z = p[2 * HH]; v.w = p[3 * HH];
        wb4[k4 * 16 + ((c & 1) * 8 + (c >> 1))] = v;
    }
    __syncthreads();   // only CTA-wide sync; halves are independent after

    const int wl   = tid2 >> 5;     // local warp 0..7 = consumed k-chunk
    const int lane = tid & 31;
    const int cq   = lane & 7;      // cols 2cq, 2cq+1
    const int bq   = lane >> 3;     // batches 4bq..4bq+3

    const int eb = tid2 >> 4;       // epilogue batch 0..15
    const int ec = tid2 & 15;       // epilogue col

    float* redh = redb + half * (2 * RED_PAR);

    for (int t = 0; t < TT; t++) {
        const int p = t & 1;
        float* red = redh + p * RED_PAR;

        // prefetch xp (this thread's own element; untouched until now)
        size_t ob = ((size_t)(B0 + eb) * TT + t) * HH + C0 + ec;
        float xp = __ldcg(&out[ob]);

        if (t > 0) {
            // wait for this chunk's 8 producer slices (64 warp-arrivals)
            const int* fl = &g_flags[g][t - 1][wl];
            while (ld_acq(fl) < 64) { }

            // compute 32 k4 directly from L2-resident h
            const char* hbase =
                (const char*)&g_h[p ^ 1][B0 + 4 * bq][32 * wl * 4];
            const float4* wp = wb4 + (32 * wl) * 16;
            ull a[4][2];
            #pragma unroll
            for (int bi = 0; bi < 4; bi++) { a[bi][0] = 0ull; a[bi][1] = 0ull; }

            #pragma unroll 2
            for (int m = 0; m < 32; m++) {
                ulonglong2 w0 = *(const ulonglong2*)(wp + m * 16 + cq);
                ulonglong2 w1 = *(const ulonglong2*)(wp + m * 16 + 8 + cq);
                ulonglong2 h0 = ldg2(hbase + 0 * 4096 + m * 16);
                ulonglong2 h1 = ldg2(hbase + 1 * 4096 + m * 16);
                ulonglong2 h2 = ldg2(hbase + 2 * 4096 + m * 16);
                ulonglong2 h3 = ldg2(hbase + 3 * 4096 + m * 16);
                a[0][0] = ffma2(h0.x, w0.x, a[0][0]);
                a[0][0] = ffma2(h0.y, w0.y, a[0][0]);
                a[0][1] = ffma2(h0.x, w1.x, a[0][1]);
                a[0][1] = ffma2(h0.y, w1.y, a[0][1]);
                a[1][0] = ffma2(h1.x, w0.x, a[1][0]);
                a[1][0] = ffma2(h1.y, w0.y, a[1][0]);
                a[1][1] = ffma2(h1.x, w1.x, a[1][1]);
                a[1][1] = ffma2(h1.y, w1.y, a[1][1]);
                a[2][0] = ffma2(h2.x, w0.x, a[2][0]);
                a[2][0] = ffma2(h2.y, w0.y, a[2][0]);
                a[2][1] = ffma2(h2.x, w1.x, a[2][1]);
                a[2][1] = ffma2(h2.y, w1.y, a[2][1]);
                a[3][0] = ffma2(h3.x, w0.x, a[3][0]);
                a[3][0] = ffma2(h3.y, w0.y, a[3][0]);
                a[3][1] = ffma2(h3.x, w1.x, a[3][1]);
                a[3][1] = ffma2(h3.y, w1.y, a[3][1]);
            }

            // horizontal add -> red[b][wl][2 cols]
            #pragma unroll
            for (int bi = 0; bi < 4; bi++) {
                float2 v0 = upk2(a[bi][0]);
                float2 v1 = upk2(a[bi][1]);
                *(float2*)&red[(4 * bq + bi) * RROW + wl * 16 + 2 * cq] =
                    make_float2(v0.x + v0.y, v1.x + v1.y);
            }
            // join this half's 8 warps (drains STS; id 1 or 2)
            asm volatile("bar.sync %0, 256;" :: "r"(half + 1) : "memory");
        }

        // epilogue: reduce 8 k-chunks, add xp, tanh, publish
        float s = xp;
        if (t > 0) {
            #pragma unroll
            for (int q = 0; q < 8; q++)
                s += red[eb * RROW + q * 16 + ec];
        }
        float r = fast_tanh(s);
        g_h[p][B0 + eb][C0 + ec] = r;
        __syncwarp();
        if (lane == 0) red_rel_add1(&g_flags[g][t][jc]);
        out[ob] = r;      // off critical path
        // red reuse across steps is safe: parity double buffer + the
        // consumer's flag-wait happens-after every reader's release.
    }
}

// =====================================================================
// Launch
// =====================================================================
extern "C" void kernel_launch(void* const* d_in, const int* in_sizes, int n_in,
                              void* d_out, int out_size)
{
    const float* x  = nullptr;
    const float* Wx = nullptr;
    const float* Wh = nullptr;
    const float* bv = nullptr;
    for (int i = 0; i < n_in; i++) {
        int s = in_sizes[i];
        if (s == BB * TT * DD)      x  = (const float*)d_in[i];
        else if (s == DD * HH)      Wx = (const float*)d_in[i];
        else if (s == HH * HH)      Wh = (const float*)d_in[i];
        else if (s == HH)           bv = (const float*)d_in[i];
    }
    float* out = (float*)d_out;

    static int configured = 0;
    if (!configured) {
        cudaFuncSetAttribute(rnn_persist,
                             cudaFuncAttributeMaxDynamicSharedMemorySize,
                             SMEM_BYTES);
        configured = 1;
    }

    dim3 g1((BB * TT) / 64, HH / 64);
    xp_gemm<<<g1, 256>>>(x, Wx, bv, out);

    rnn_persist<<<128, 512, SMEM_BYTES>>>(out, Wh);
}

// round 10
// speedup vs baseline: 1.2996x; 1.2996x over previous
#include <cuda_runtime.h>
#include <cuda_bf16.h>
#include <cstddef>

// x[64,512,128] @ Wx[128,1024] + b -> XP (in d_out); then
// h_t = tanh(xp_t + h_{t-1} @ Wh[1024,1024]); out[b,t,:] = h_t.
#define BB 64
#define TT 512
#define DD 128
#define HH 1024

typedef unsigned long long ull;

__device__ __forceinline__ ull pk2(float lo, float hi) {
    ull r; asm("mov.b64 %0, {%1, %2};" : "=l"(r) : "f"(lo), "f"(hi)); return r;
}
__device__ __forceinline__ float2 upk2(ull v) {
    float lo, hi; asm("mov.b64 {%0, %1}, %2;" : "=f"(lo), "=f"(hi) : "l"(v));
    return make_float2(lo, hi);
}
__device__ __forceinline__ ull ffma2(ull a, ull b, ull c) {
    ull d; asm("fma.rn.f32x2 %0, %1, %2, %3;" : "=l"(d) : "l"(a), "l"(b), "l"(c));
    return d;
}
__device__ __forceinline__ int ld_acq(const int* p) {
    int v; asm volatile("ld.acquire.gpu.global.s32 %0, [%1];" : "=r"(v) : "l"(p));
    return v;
}
__device__ __forceinline__ void red_rel_add1(int* p) {
    asm volatile("red.release.gpu.global.add.s32 [%0], 1;" :: "l"(p) : "memory");
}
// fast tanh: exp-based, ~1e-6 rel err; clamp avoids inf/inf.
__device__ __forceinline__ float fast_tanh(float x) {
    x = fminf(fmaxf(x, -15.f), 15.f);
    float e = __expf(x + x);
    return __fdividef(e - 1.f, e + 1.f);
}

// ---------- global scratch ----------
__device__ float g_h[2][BB][HH];         // h double buffer, row-major [b][k]
__device__ int   g_flags[4][TT][8];      // (group, step, k-chunk) warp arrivals

// =====================================================================
// Kernel 1: XP = x @ Wx + b  -> d_out   (M=32768, K=128, N=1024)
// Block (0,0) also resets the step flags.
// =====================================================================
__global__ __launch_bounds__(256) void xp_gemm(
    const float* __restrict__ x, const float* __restrict__ Wx,
    const float* __restrict__ bias, float* __restrict__ out)
{
    __shared__ float xs[64 * 68];
    __shared__ float ws[64 * 64];

    const int tid = threadIdx.x;
    if (blockIdx.x == 0 && blockIdx.y == 0) {
        int* f = &g_flags[0][0][0];
        #pragma unroll
        for (int i = tid; i < 4 * TT * 8; i += 256) f[i] = 0;
    }

    const int m0 = blockIdx.x * 64;
    const int n0 = blockIdx.y * 64;
    const int ty = tid >> 4;
    const int tx = tid & 15;

    ull acc01[4] = {0ull, 0ull, 0ull, 0ull};
    ull acc23[4] = {0ull, 0ull, 0ull, 0ull};

    for (int k0 = 0; k0 < DD; k0 += 64) {
        __syncthreads();
        #pragma unroll
        for (int i = tid; i < 1024; i += 256) {
            int r = i >> 4, q = i & 15;
            ((float4*)xs)[r * 17 + q] =
                *(const float4*)&x[(size_t)(m0 + r) * DD + k0 + 4 * q];
        }
        #pragma unroll
        for (int i = tid; i < 1024; i += 256) {
            int r = i >> 4, q = i & 15;
            ((float4*)ws)[i] =
                *(const float4*)&Wx[(size_t)(k0 + r) * HH + n0 + 4 * q];
        }
        __syncthreads();

        #pragma unroll 8
        for (int kk = 0; kk < 64; kk++) {
            ulonglong2 wv = *(const ulonglong2*)&ws[kk * 64 + 4 * tx];
            #pragma unroll
            for (int i = 0; i < 4; i++) {
                float a = xs[(4 * ty + i) * 68 + kk];
                ull aa = pk2(a, a);
                acc01[i] = ffma2(aa, wv.x, acc01[i]);
                acc23[i] = ffma2(aa, wv.y, acc23[i]);
            }
        }
    }

    float4 bv = *(const float4*)&bias[n0 + 4 * tx];
    #pragma unroll
    for (int i = 0; i < 4; i++) {
        float2 p0 = upk2(acc01[i]);
        float2 p1 = upk2(acc23[i]);
        float4 r;
        r.x = p0.x + bv.x; r.y = p0.y + bv.y;
        r.z = p1.x + bv.z; r.w = p1.y + bv.w;
        *(float4*)&out[(size_t)(m0 + 4 * ty + i) * HH + n0 + 4 * tx] = r;
    }
}

// =====================================================================
// Kernel 2: persistent recurrence, TWO independent chains per SM with
// smem-staged operands. 128 CTAs x 512 threads (16 warps).
// CTA cid: col slice j = cid&63 (16 cols; Wh slice SHARED by halves).
//   half 0 (warps 0-7):  group cid>>6      (0 or 1)
//   half 1 (warps 8-15): group cid>>6 + 2  (2 or 3)
// Per half: warp ks stages+consumes k-chunk ks (128 k x 16 batches, 8KB)
// in smem with XOR swizzle slot = b ^ (k4&15): staging stores fully
// bank-spread, compute loads 1-wavefront broadcast. Lane (cq=lane&7,
// bq=lane>>3): 4 batches x 2 cols packed-over-k.
// red[half][parity][8][16][16] (EVEN row stride -> 8B-aligned float2).
// ONE bar.sync(half+1,256) per step. No 2nd barrier: flag[t+1] full
// transitively implies epi(t) done everywhere (each producer CTA's
// warps consumed all 8 chunk flags of step t, incl. our epi arrivals),
// so parity-buffered red reuse is ordered.
// Flags target 64 = 8 producer slices x 8 epi warps.
// =====================================================================
#define WB_F4   4096                      /* Wh  [256 k4][16 slots] = 64KB */
#define HB_F4   4096                      /* h per half [256 k4][16] = 64KB */
#define RED_ROW 16
#define RED_PAR (8 * 16 * RED_ROW)        /* 2048 floats */
#define SMEM_BYTES (WB_F4*16 + 2*HB_F4*16 + 4*RED_PAR*4)  /* 229,376 B */

__global__ __launch_bounds__(512, 1) void rnn_persist(
    float* __restrict__ out, const float* __restrict__ Wh)
{
    extern __shared__ float4 sm4[];
    float4* wb4  = sm4;                       // [256][16]
    float4* hbb  = sm4 + WB_F4;               // [2][256][16]
    float*  redb = (float*)(sm4 + WB_F4 + 2 * HB_F4); // [2][2][RED_PAR]

    const int tid  = threadIdx.x;
    const int half = tid >> 8;
    const int tid2 = tid & 255;
    const int j    = blockIdx.x & 63;
    const int g    = (blockIdx.x >> 6) + 2 * half;
    const int B0   = 16 * g;
    const int C0   = 16 * j;
    const int jc   = j >> 3;                  // chunk this slice feeds

    // one-time: Wh slice [1024 k][16 c] K-transposed into float4 blocks;
    // col c at slot (c&1)*8 + (c>>1)  (even cols 0-7, odd cols 8-15).
    for (int idx = tid; idx < WB_F4; idx += 512) {
        int k4 = idx >> 4, c = idx & 15;
        const float* p = &Wh[(size_t)(4 * k4) * HH + C0 + c];
        float4 v;
        v.x = p[0]; v.y = p[HH]; v.z = p[2 * HH]; v.w = p[3 * HH];
        wb4[k4 * 16 + ((c & 1) * 8 + (c >> 1))] = v;
    }
    __syncthreads();   // only CTA-wide sync; halves independent after this

    const int ks   = (tid2 >> 5);   // local warp 0..7 = its k-chunk
    const int lane = tid & 31;
    const int cq   = lane & 7;      // cols 2cq, 2cq+1
    const int bq   = lane >> 3;     // batches 4bq..4bq+3

    const int kl = lane & 15;       // staging: k4 sub-index
    const int bh = lane >> 4;       // staging: batch half

    const int eb = tid2 >> 4;       // epilogue batch 0..15
    const int ec = tid2 & 15;       // epilogue col 0..15

    float4* hb   = hbb + half * HB_F4;
    float*  redh = redb + half * (2 * RED_PAR);

    for (int t = 0; t < TT; t++) {
        const int p = t & 1;
        float* red = redh + p * RED_PAR;

        // prefetch xp (this thread's own output element)
        size_t ob = ((size_t)(B0 + eb) * TT + t) * HH + C0 + ec;
        float xp = __ldcg(&out[ob]);

        if (t > 0) {
            // wait for this chunk's 8 producer slices (64 warp-arrivals)
            const int* fl = &g_flags[g][t - 1][ks];
            while (ld_acq(fl) < 64) { }

            // stage this warp's 128-k chunk of h_{t-1}: 16 LDG.128/lane,
            // XOR-swizzled smem slots (bank-spread stores)
            {
                const float4* src = (const float4*)&g_h[p ^ 1][B0][0]; // [16][256]
                const int k4a = 32 * ks + kl;
                const int k4b = k4a + 16;
                #pragma unroll
                for (int i = 0; i < 8; i++) {
                    int b = 8 * bh + i;
                    float4 va = __ldcg(src + b * 256 + k4a);
                    float4 vb = __ldcg(src + b * 256 + k4b);
                    hb[k4a * 16 + (b ^ kl)] = va;
                    hb[k4b * 16 + (b ^ kl)] = vb;
                }
            }
            __syncwarp();

            // compute 32 k4: per iter 6 one-wavefront LDS.128 + 16 ffma2
            const float4* hrow = hb + (32 * ks) * 16;
            const float4* wp   = wb4 + (32 * ks) * 16;
            ull a[4][2];
            #pragma unroll
            for (int bi = 0; bi < 4; bi++) { a[bi][0] = 0ull; a[bi][1] = 0ull; }

            #pragma unroll 4
            for (int m = 0; m < 32; m++) {
                const int sl = m & 15;
                ulonglong2 w0 = *(const ulonglong2*)(wp + m * 16 + cq);
                ulonglong2 w1 = *(const ulonglong2*)(wp + m * 16 + 8 + cq);
                ulonglong2 h0 = *(const ulonglong2*)(hrow + m * 16 + ((4 * bq + 0) ^ sl));
                ulonglong2 h1 = *(const ulonglong2*)(hrow + m * 16 + ((4 * bq + 1) ^ sl));
                ulonglong2 h2 = *(const ulonglong2*)(hrow + m * 16 + ((4 * bq + 2) ^ sl));
                ulonglong2 h3 = *(const ulonglong2*)(hrow + m * 16 + ((4 * bq + 3) ^ sl));
                a[0][0] = ffma2(h0.x, w0.x, a[0][0]);
                a[0][0] = ffma2(h0.y, w0.y, a[0][0]);
                a[0][1] = ffma2(h0.x, w1.x, a[0][1]);
                a[0][1] = ffma2(h0.y, w1.y, a[0][1]);
                a[1][0] = ffma2(h1.x, w0.x, a[1][0]);
                a[1][0] = ffma2(h1.y, w0.y, a[1][0]);
                a[1][1] = ffma2(h1.x, w1.x, a[1][1]);
                a[1][1] = ffma2(h1.y, w1.y, a[1][1]);
                a[2][0] = ffma2(h2.x, w0.x, a[2][0]);
                a[2][0] = ffma2(h2.y, w0.y, a[2][0]);
                a[2][1] = ffma2(h2.x, w1.x, a[2][1]);
                a[2][1] = ffma2(h2.y, w1.y, a[2][1]);
                a[3][0] = ffma2(h3.x, w0.x, a[3][0]);
                a[3][0] = ffma2(h3.y, w0.y, a[3][0]);
                a[3][1] = ffma2(h3.x, w1.x, a[3][1]);
                a[3][1] = ffma2(h3.y, w1.y, a[3][1]);
            }

            // horizontal add -> red[ks][b][c] (even stride, 8B-aligned)
            #pragma unroll
            for (int bi = 0; bi < 4; bi++) {
                float2 v0 = upk2(a[bi][0]);
                float2 v1 = upk2(a[bi][1]);
                *(float2*)&red[(ks * 16 + 4 * bq + bi) * RED_ROW + 2 * cq] =
                    make_float2(v0.x + v0.y, v1.x + v1.y);
            }
        }
        // join this half's 8 warps (drains STS)
        asm volatile("bar.sync %0, 256;" :: "r"(half + 1) : "memory");

        // epilogue: reduce 8 k-chunks, add xp, tanh, publish
        float s = xp;
        if (t > 0) {
            #pragma unroll
            for (int q = 0; q < 8; q++)
                s += red[(q * 16 + eb) * RED_ROW + ec];
        }
        float r = fast_tanh(s);
        g_h[p][B0 + eb][C0 + ec] = r;
        __syncwarp();
        if (lane == 0) red_rel_add1(&g_flags[g][t][jc]);
        out[ob] = r;     // off critical path
    }
}

// =====================================================================
// Launch
// =====================================================================
extern "C" void kernel_launch(void* const* d_in, const int* in_sizes, int n_in,
                              void* d_out, int out_size)
{
    const float* x  = nullptr;
    const float* Wx = nullptr;
    const float* Wh = nullptr;
    const float* bv = nullptr;
    for (int i = 0; i < n_in; i++) {
        int s = in_sizes[i];
        if (s == BB * TT * DD)      x  = (const float*)d_in[i];
        else if (s == DD * HH)      Wx = (const float*)d_in[i];
        else if (s == HH * HH)      Wh = (const float*)d_in[i];
        else if (s == HH)           bv = (const float*)d_in[i];
    }
    float* out = (float*)d_out;

    static int configured = 0;
    if (!configured) {
        cudaFuncSetAttribute(rnn_persist,
                             cudaFuncAttributeMaxDynamicSharedMemorySize,
                             SMEM_BYTES);
        configured = 1;
    }

    dim3 g1((BB * TT) / 64, HH / 64);
    xp_gemm<<<g1, 256>>>(x, Wx, bv, out);

    rnn_persist<<<128, 512, SMEM_BYTES>>>(out, Wh);
}